// round 7
// baseline (speedup 1.0000x reference)
#include <cuda_runtime.h>

// ---------------------------------------------------------------------------
// B=16, N=7, Lq=256, Lp=512, D=768, S=12, Wq=200, Wp=400
// word slots: q 3200, p 6400, n 44800 -> 54400
// out floats: q_pooled[0,12288) p_pooled[12288,24576)
//             q_logits[24576,62976) p_logits[62976,139776) n_pooled[139776,225792)
// ---------------------------------------------------------------------------
#define TOTAL_WORDS 54400
#define OFF_QPOOL 0
#define OFF_PPOOL 12288
#define OFF_QLOG  24576
#define OFF_PLOG  62976
#define OFF_NPOOL 139776

// g_acc[w*13 + 0..11] = logit sums, [w*13+12] = count
__device__ float g_acc[TOTAL_WORDS * 13];
__device__ float g_coef[TOTAL_WORDS];
__device__ unsigned g_ticket;

typedef unsigned long long u64;

__device__ __forceinline__ u64 pack2(float x) {
    u64 r; asm("mov.b64 %0, {%1, %1};" : "=l"(r) : "f"(x)); return r;
}
__device__ __forceinline__ u64 pack2(float lo, float hi) {
    u64 r; asm("mov.b64 %0, {%1, %2};" : "=l"(r) : "f"(lo), "f"(hi)); return r;
}
__device__ __forceinline__ void fma2(u64& a, u64 x, u64 y) {
    asm("fma.rn.f32x2 %0, %1, %2, %0;" : "+l"(a) : "l"(x), "l"(y));
}
__device__ __forceinline__ u64 add2(u64 x, u64 y) {
    u64 r; asm("add.rn.f32x2 %0, %1, %2;" : "=l"(r) : "l"(x), "l"(y)); return r;
}
__device__ __forceinline__ float2 unpack2(u64 v) {
    float2 r; asm("mov.b64 {%0, %1}, %2;" : "=f"(r.x), "=f"(r.y) : "l"(v)); return r;
}

// ---------------------------------------------------------------------------
// Kernel A: per-token projection h[768]@W[768x12] + segment atomics.
// 256-thread blocks (weight table amortized over 8 warps), 3 CTAs/SM ->
// 24 warps/SM. Per warp-pass: 8 tokens (tt=2), dynamic ticket balancing.
//   sub = lane&7 covers d = sub*4 + 32*i + k (i 0..23, k 0..3)
//   grp = lane>>3 (0..3), tokens = grp + 4*tt
// Software pipeline: 3 rotating 2-float4 buffers, loads 2-3 blocks ahead.
// acc 24 regs + bufs 24 regs -> fits 85-reg cap of (256,3) without spills.
// Weights: smem chunks [c][k*6+j], pitch 26 u64; per k: 3x LDS.128,
// sub byte offsets mod 128 = {0,80,32,112,64,16,96,48} -> conflict-free,
// 4-way broadcast across grps.
// ---------------------------------------------------------------------------
#define WSLOT 26
#define NPASS_TOTAL 8704
#define KA_BLOCKS 444   // 148 SM * 3

#define KA_LD(I, V0, V1)                                                       \
    {                                                                          \
        V0 = __ldcg((const float4*)(hbg +        (I) * 32));                   \
        V1 = __ldcg((const float4*)(hbg + 3072 + (I) * 32));                   \
    }

#define KA_COMPUTE(I, A0, A1)                                                  \
    {                                                                          \
        const u64* wr = swl + (I) * (8 * WSLOT);                               \
        _Pragma("unroll")                                                      \
        for (int k = 0; k < 4; k++) {                                          \
            u64 h0 = pack2(((const float*)&A0)[k]);                            \
            u64 h1 = pack2(((const float*)&A1)[k]);                            \
            ulonglong2 w01 = *(const ulonglong2*)(wr + k * 6);                 \
            ulonglong2 w23 = *(const ulonglong2*)(wr + k * 6 + 2);             \
            ulonglong2 w45 = *(const ulonglong2*)(wr + k * 6 + 4);             \
            fma2(acc[0][0], h0, w01.x); fma2(acc[0][1], h0, w01.y);            \
            fma2(acc[0][2], h0, w23.x); fma2(acc[0][3], h0, w23.y);            \
            fma2(acc[0][4], h0, w45.x); fma2(acc[0][5], h0, w45.y);            \
            fma2(acc[1][0], h1, w01.x); fma2(acc[1][1], h1, w01.y);            \
            fma2(acc[1][2], h1, w23.x); fma2(acc[1][3], h1, w23.y);            \
            fma2(acc[1][4], h1, w45.x); fma2(acc[1][5], h1, w45.y);            \
        }                                                                      \
    }

__global__ __launch_bounds__(256, 3) void kA(
    const float* __restrict__ qh, const float* __restrict__ ph, const float* __restrict__ nh,
    const int* __restrict__ qw, const int* __restrict__ pw, const int* __restrict__ nwid,
    const float* __restrict__ projw)
{
    __shared__ __align__(16) u64 sw[192 * WSLOT];   // 39936 bytes
    for (int idx = threadIdx.x; idx < 768 * 6; idx += 256) {
        int d = idx / 6, j = idx % 6;
        sw[(d >> 2) * WSLOT + (d & 3) * 6 + j] =
            pack2(projw[d * 12 + 2 * j], projw[d * 12 + 2 * j + 1]);
    }
    __syncthreads();

    const int lane = threadIdx.x & 31;
    const int sub  = lane & 7;
    const int grp  = lane >> 3;
    const u64* swl = sw + sub * WSLOT;

    for (;;) {
        unsigned t;
        if (lane == 0) t = atomicAdd(&g_ticket, 1u);
        t = __shfl_sync(0xffffffffu, t, 0);
        if (t >= NPASS_TOTAL) break;
        const int p = (int)t;

        const float* hid; const int* wid; int logL, W, wb, lp;
        if (p < 512)       { hid = qh; wid = qw;   logL = 8; W = 200; wb = 0;    lp = p; }
        else if (p < 1536) { hid = ph; wid = pw;   logL = 9; W = 400; wb = 3200; lp = p - 512; }
        else               { hid = nh; wid = nwid; logL = 9; W = 400; wb = 9600; lp = p - 1536; }

        const int tokBase = lp << 3;                 // 8 tokens
        const int m = tokBase >> logL;
        const float* hbg = hid + (size_t)tokBase * 768 + (size_t)grp * 768 + sub * 4;

        u64 acc[2][6];
        #pragma unroll
        for (int j = 0; j < 6; j++) { acc[0][j] = 0ull; acc[1][j] = 0ull; }

        float4 A0, A1, B0, B1, C0, C1;
        KA_LD(0, A0, A1);
        KA_LD(1, B0, B1);

        #pragma unroll 1
        for (int i = 0; i < 21; i += 3) {
            KA_LD(i + 2, C0, C1);
            KA_COMPUTE(i, A0, A1);
            KA_LD(i + 3, A0, A1);
            KA_COMPUTE(i + 1, B0, B1);
            KA_LD(i + 4, B0, B1);
            KA_COMPUTE(i + 2, C0, C1);
        }
        KA_LD(23, C0, C1);
        KA_COMPUTE(21, A0, A1);
        KA_COMPUTE(22, B0, B1);
        KA_COMPUTE(23, C0, C1);

        // reduce across the 8 sub-lanes (xor 1,2,4 stay inside the octet)
        #pragma unroll
        for (int tt = 0; tt < 2; tt++)
            #pragma unroll
            for (int j = 0; j < 6; j++) {
                u64 v = acc[tt][j];
                v = add2(v, __shfl_xor_sync(0xffffffffu, v, 1));
                v = add2(v, __shfl_xor_sync(0xffffffffu, v, 2));
                v = add2(v, __shfl_xor_sync(0xffffffffu, v, 4));
                acc[tt][j] = v;
            }

        if (sub == 0) {
            #pragma unroll
            for (int tt = 0; tt < 2; tt++) {
                int tok = tokBase + grp + 4 * tt;
                float* ls = g_acc + (size_t)(wb + m * W + wid[tok]) * 13;
                #pragma unroll
                for (int j = 0; j < 6; j++) {
                    float2 f = unpack2(acc[tt][j]);
                    atomicAdd(ls + 2 * j,     f.x);
                    atomicAdd(ls + 2 * j + 1, f.y);
                }
                atomicAdd(ls + 12, 1.0f);
            }
        }
    }
}

// ---------------------------------------------------------------------------
// Kernel B: per sample — scope softmax -> importance, masked word softmax ->
// per-word coefficient weight/count; writes q/p logits. 144 blocks x 128.
// ---------------------------------------------------------------------------
__global__ __launch_bounds__(128) void kB(const float* __restrict__ projb,
                                          const float* __restrict__ simp,
                                          float* __restrict__ out)
{
    const int blk = blockIdx.x;
    int W, wb; float* lout = nullptr;
    if (blk < 16)      { W = 200; wb = blk * 200;                    lout = out + OFF_QLOG + blk * 200 * 12; }
    else if (blk < 32) { int m = blk - 16; W = 400; wb = 3200 + m * 400; lout = out + OFF_PLOG + m * 400 * 12; }
    else               { int m = blk - 32; W = 400; wb = 9600 + m * 400; }

    __shared__ float impbuf[400];
    __shared__ float red[4];
    const int tid = threadIdx.x;

    float b[12], si[12];
    #pragma unroll
    for (int s = 0; s < 12; s++) { b[s] = projb[s]; si[s] = simp[s]; }

    for (int w = tid; w < W; w += 128) {
        const float* ls = g_acc + (size_t)(wb + w) * 13;
        float c = ls[12];
        float imp;
        if (c > 0.f) {
            float l[12], mx = -1e30f;
            float invc = 1.f / c;
            #pragma unroll
            for (int s = 0; s < 12; s++) {
                l[s] = ls[s] * invc + b[s];
                mx = fmaxf(mx, l[s]);
            }
            float se = 0.f, ai = 0.f;
            #pragma unroll
            for (int s = 0; s < 12; s++) {
                float e = __expf(l[s] - mx);
                se += e; ai += e * si[s];
            }
            imp = ai / se;
            if (lout) {
                #pragma unroll
                for (int s = 0; s < 12; s++) lout[w * 12 + s] = l[s];
            }
        } else {
            imp = -1e4f;
            if (lout) {
                #pragma unroll
                for (int s = 0; s < 12; s++) lout[w * 12 + s] = 0.f;
            }
        }
        impbuf[w] = imp;
    }
    __syncthreads();

    float mx = -1e30f;
    for (int w = tid; w < W; w += 128) mx = fmaxf(mx, impbuf[w]);
    #pragma unroll
    for (int o = 16; o; o >>= 1) mx = fmaxf(mx, __shfl_xor_sync(0xffffffffu, mx, o));
    if ((tid & 31) == 0) red[tid >> 5] = mx;
    __syncthreads();
    mx = fmaxf(fmaxf(red[0], red[1]), fmaxf(red[2], red[3]));
    __syncthreads();

    float se = 0.f;
    for (int w = tid; w < W; w += 128) se += __expf(impbuf[w] - mx);
    #pragma unroll
    for (int o = 16; o; o >>= 1) se += __shfl_xor_sync(0xffffffffu, se, o);
    if ((tid & 31) == 0) red[tid >> 5] = se;
    __syncthreads();
    se = red[0] + red[1] + red[2] + red[3];
    const float inv = 1.f / se;

    for (int w = tid; w < W; w += 128) {
        float c = g_acc[(size_t)(wb + w) * 13 + 12];
        g_coef[wb + w] = (c > 0.f) ? (__expf(impbuf[w] - mx) * inv) / c : 0.f;
    }
}

// ---------------------------------------------------------------------------
// Kernel C: pooled[m,:] += sum over 64-token slab coef[m, wid] * h[m,tok,:]
// 1088 blocks x 192 threads. REVERSED chunk order: earliest blocks read the
// data kA touched last (still resident in 126MB L2) -> ~half the reads hit L2.
// Default cache policy (no ldcs) to exploit/preserve residency.
// ---------------------------------------------------------------------------
__global__ __launch_bounds__(192) void kC(
    const float* __restrict__ qh, const float* __restrict__ ph, const float* __restrict__ nh,
    const int* __restrict__ qw, const int* __restrict__ pw, const int* __restrict__ nwid,
    float* __restrict__ out)
{
    const int blk = 1087 - blockIdx.x;   // reverse order
    const float* hid; const int* wid; int L, wb, m, slab; float* po;
    if (blk < 64)       { m = blk >> 2;  slab = blk & 3; hid = qh; wid = qw;   L = 256; wb = m * 200;        po = out + OFF_QPOOL + m * 768; }
    else if (blk < 192) { int b2 = blk - 64;  m = b2 >> 3; slab = b2 & 7; hid = ph; wid = pw;   L = 512; wb = 3200 + m * 400; po = out + OFF_PPOOL + m * 768; }
    else                { int b2 = blk - 192; m = b2 >> 3; slab = b2 & 7; hid = nh; wid = nwid; L = 512; wb = 9600 + m * 400; po = out + OFF_NPOOL + m * 768; }

    __shared__ float cf[64];
    const int tid = threadIdx.x;
    const int t0 = slab * 64;
    if (tid < 64) cf[tid] = g_coef[wb + wid[m * L + t0 + tid]];
    __syncthreads();

    const float* hp = hid + (size_t)(m * L + t0) * 768 + tid * 4;
    float ax = 0.f, ay = 0.f, az = 0.f, aw = 0.f;
    #pragma unroll 8
    for (int t = 0; t < 64; t++) {
        float c = cf[t];
        float4 v = __ldcg((const float4*)(hp + (size_t)t * 768));
        ax += c * v.x; ay += c * v.y; az += c * v.z; aw += c * v.w;
    }
    float* o = po + tid * 4;
    atomicAdd(o + 0, ax);
    atomicAdd(o + 1, ay);
    atomicAdd(o + 2, az);
    atomicAdd(o + 3, aw);
}

// ---------------------------------------------------------------------------
extern "C" void kernel_launch(void* const* d_in, const int* in_sizes, int n_in,
                              void* d_out, int out_size)
{
    const float* qh    = (const float*)d_in[0];
    const float* ph    = (const float*)d_in[1];
    const float* nh    = (const float*)d_in[2];
    const float* projw = (const float*)d_in[3];
    const float* projb = (const float*)d_in[4];
    const float* simp  = (const float*)d_in[5];
    const int*   qw    = (const int*)d_in[6];
    const int*   pw    = (const int*)d_in[7];
    const int*   nwid  = (const int*)d_in[8];
    float* out = (float*)d_out;

    void* pacc = nullptr; cudaGetSymbolAddress(&pacc, g_acc);
    void* ptck = nullptr; cudaGetSymbolAddress(&ptck, g_ticket);
    cudaMemsetAsync(pacc, 0, sizeof(float) * TOTAL_WORDS * 13);
    cudaMemsetAsync(ptck, 0, sizeof(unsigned));
    cudaMemsetAsync(out + OFF_QPOOL, 0, sizeof(float) * 24576);   // q_pooled + p_pooled
    cudaMemsetAsync(out + OFF_NPOOL, 0, sizeof(float) * 86016);   // n_pooled

    kA<<<KA_BLOCKS, 256>>>(qh, ph, nh, qw, pw, nwid, projw);
    kB<<<144, 128>>>(projb, simp, out);
    kC<<<1088, 192>>>(qh, ph, nh, qw, pw, nwid, out);
}

// round 8
// speedup vs baseline: 1.0828x; 1.0828x over previous
#include <cuda_runtime.h>

// ---------------------------------------------------------------------------
// B=16, N=7, Lq=256, Lp=512, D=768, S=12, Wq=200, Wp=400
// word slots: q 3200, p 6400, n 44800 -> 54400
// out floats: q_pooled[0,12288) p_pooled[12288,24576)
//             q_logits[24576,62976) p_logits[62976,139776) n_pooled[139776,225792)
// ---------------------------------------------------------------------------
#define TOTAL_WORDS 54400
#define OFF_QPOOL 0
#define OFF_PPOOL 12288
#define OFF_QLOG  24576
#define OFF_PLOG  62976
#define OFF_NPOOL 139776

__device__ float g_acc[TOTAL_WORDS * 13];   // 12 logit sums + count
__device__ float g_coef[TOTAL_WORDS];
__device__ unsigned g_ticket;

typedef unsigned long long u64;

__device__ __forceinline__ u64 pack2(float x) {
    u64 r; asm("mov.b64 %0, {%1, %1};" : "=l"(r) : "f"(x)); return r;
}
__device__ __forceinline__ u64 pack2(float lo, float hi) {
    u64 r; asm("mov.b64 %0, {%1, %2};" : "=l"(r) : "f"(lo), "f"(hi)); return r;
}
__device__ __forceinline__ void fma2(u64& a, u64 x, u64 y) {
    asm("fma.rn.f32x2 %0, %1, %2, %0;" : "+l"(a) : "l"(x), "l"(y));
}
__device__ __forceinline__ u64 add2(u64 x, u64 y) {
    u64 r; asm("add.rn.f32x2 %0, %1, %2;" : "=l"(r) : "l"(x), "l"(y)); return r;
}
__device__ __forceinline__ float2 unpack2(u64 v) {
    float2 r; asm("mov.b64 {%0, %1}, %2;" : "=f"(r.x), "=f"(r.y) : "l"(v)); return r;
}

// ---------------------------------------------------------------------------
// Kernel A: per-token projection h[768]@W[768x12] + segment atomics, with
// cp.async smem staging (in-flight data lives in SMEM, not registers).
//
// 256 threads (8 warps), 2 CTAs/SM. Chunk = 128 tokens (contiguous rows).
// Stage(i) = all 128 tokens' bytes [i*128, i*128+128) of their 3072B rows
//          = 16KB, ring of 4 stages, cp.async.cg 16B x4 per thread per stage.
// Staging addressing: warp op j covers 4 tokens x full 128B line (optimal
// 4 wavefronts per op). Consumption: warp w owns tokens 16w..16w+15 with the
// proven tt=4 + grp layout; h read back via conflict-free LDS.128.
// Weights: smem chunks [c][k*6+j], pitch 26 u64 (39936B); per k 3x LDS.128,
// sub offsets mod 128 = {0,80,32,112,64,16,96,48} -> conflict-free broadcast.
// Dynamic smem: 39936 + 4*16384 = 105472B -> 2 CTAs/SM.
// ---------------------------------------------------------------------------
#define WSLOT 26
#define STAGE_BYTES 16384
#define NCHUNKS 544          // q 32, p 64, n 448 chunks of 128 tokens
#define KA_BLOCKS 296        // 148 SM * 2
#define KA_SMEM (39936 + 4 * STAGE_BYTES)

__device__ __forceinline__ void cp16(unsigned dst, const void* src) {
    asm volatile("cp.async.cg.shared.global [%0], [%1], 16;" :: "r"(dst), "l"(src));
}

#define KA_ISSUE(S)                                                            \
    {                                                                          \
        const unsigned st = ((S) & 3) * STAGE_BYTES + hbuf_u32;                \
        _Pragma("unroll")                                                      \
        for (int j = 0; j < 4; j++) {                                          \
            const int tok = grp + 4 * (wrp * 4 + j);                           \
            cp16(st + tok * 128 + sub * 16,                                    \
                 hb + (size_t)tok * 768 + (S) * 32 + sub * 4);                 \
        }                                                                      \
        asm volatile("cp.async.commit_group;" ::: "memory");                   \
    }

#define KA_WAIT(N) asm volatile("cp.async.wait_group %0;" :: "n"(N) : "memory")

#define KA_CONSUME(I)                                                          \
    {                                                                          \
        const char* bp = hbuf + ((I) & 3) * STAGE_BYTES + tbase * 128 + sub * 16; \
        float4 A0 = *(const float4*)(bp);                                      \
        float4 A1 = *(const float4*)(bp + 512);                                \
        float4 A2 = *(const float4*)(bp + 1024);                               \
        float4 A3 = *(const float4*)(bp + 1536);                               \
        const u64* wr = swl + (I) * (8 * WSLOT);                               \
        _Pragma("unroll")                                                      \
        for (int k = 0; k < 4; k++) {                                          \
            u64 h0 = pack2(((const float*)&A0)[k]);                            \
            u64 h1 = pack2(((const float*)&A1)[k]);                            \
            u64 hv2 = pack2(((const float*)&A2)[k]);                           \
            u64 h3 = pack2(((const float*)&A3)[k]);                            \
            ulonglong2 w01 = *(const ulonglong2*)(wr + k * 6);                 \
            ulonglong2 w23 = *(const ulonglong2*)(wr + k * 6 + 2);             \
            ulonglong2 w45 = *(const ulonglong2*)(wr + k * 6 + 4);             \
            fma2(acc[0][0], h0, w01.x); fma2(acc[0][1], h0, w01.y);            \
            fma2(acc[0][2], h0, w23.x); fma2(acc[0][3], h0, w23.y);            \
            fma2(acc[0][4], h0, w45.x); fma2(acc[0][5], h0, w45.y);            \
            fma2(acc[1][0], h1, w01.x); fma2(acc[1][1], h1, w01.y);            \
            fma2(acc[1][2], h1, w23.x); fma2(acc[1][3], h1, w23.y);            \
            fma2(acc[1][4], h1, w45.x); fma2(acc[1][5], h1, w45.y);            \
            fma2(acc[2][0], hv2, w01.x); fma2(acc[2][1], hv2, w01.y);          \
            fma2(acc[2][2], hv2, w23.x); fma2(acc[2][3], hv2, w23.y);          \
            fma2(acc[2][4], hv2, w45.x); fma2(acc[2][5], hv2, w45.y);          \
            fma2(acc[3][0], h3, w01.x); fma2(acc[3][1], h3, w01.y);            \
            fma2(acc[3][2], h3, w23.x); fma2(acc[3][3], h3, w23.y);            \
            fma2(acc[3][4], h3, w45.x); fma2(acc[3][5], h3, w45.y);            \
        }                                                                      \
    }

__global__ __launch_bounds__(256, 2) void kA(
    const float* __restrict__ qh, const float* __restrict__ ph, const float* __restrict__ nh,
    const int* __restrict__ qw, const int* __restrict__ pw, const int* __restrict__ nwid,
    const float* __restrict__ projw)
{
    extern __shared__ __align__(16) char dsm[];
    u64* sw = (u64*)dsm;                       // 39936 B weight table
    char* hbuf = dsm + 39936;                  // 4 x 16KB stages
    __shared__ unsigned s_t;

    unsigned hbuf_u32;
    {
        unsigned base;
        asm("{ .reg .u64 t; cvta.to.shared.u64 t, %1; cvt.u32.u64 %0, t; }"
            : "=r"(base) : "l"(hbuf));
        hbuf_u32 = base;
    }

    for (int idx = threadIdx.x; idx < 768 * 6; idx += 256) {
        int d = idx / 6, j = idx % 6;
        sw[(d >> 2) * WSLOT + (d & 3) * 6 + j] =
            pack2(projw[d * 12 + 2 * j], projw[d * 12 + 2 * j + 1]);
    }
    __syncthreads();

    const int tid  = threadIdx.x;
    const int lane = tid & 31;
    const int wrp  = tid >> 5;     // 0..7
    const int sub  = lane & 7;
    const int grp  = lane >> 3;
    const int tbase = 16 * wrp + grp;
    const u64* swl = sw + sub * WSLOT;

    for (;;) {
        if (tid == 0) s_t = atomicAdd(&g_ticket, 1u);
        __syncthreads();
        const int c = (int)s_t;
        if (c >= NCHUNKS) break;

        const float* hid; const int* wid; int L, W, wb, m, slab;
        if (c < 32)      { hid = qh; wid = qw;   L = 256; W = 200; wb = 0;    m = c >> 1;  slab = c & 1; }
        else if (c < 96) { int cc = c - 32; hid = ph; wid = pw;   L = 512; W = 400; wb = 3200; m = cc >> 2; slab = cc & 3; }
        else             { int cc = c - 96; hid = nh; wid = nwid; L = 512; W = 400; wb = 9600; m = cc >> 2; slab = cc & 3; }
        const int tokBase = m * L + slab * 128;
        const float* hb = hid + (size_t)tokBase * 768;

        u64 acc[4][6];
        #pragma unroll
        for (int tt = 0; tt < 4; tt++)
            #pragma unroll
            for (int j = 0; j < 6; j++) acc[tt][j] = 0ull;

        KA_ISSUE(0); KA_ISSUE(1); KA_ISSUE(2);

        #pragma unroll 1
        for (int i = 0; i < 21; i++) {
            KA_WAIT(2);
            __syncthreads();
            KA_ISSUE(i + 3);
            KA_CONSUME(i);
        }
        KA_WAIT(2); __syncthreads(); KA_CONSUME(21);
        KA_WAIT(1); __syncthreads(); KA_CONSUME(22);
        KA_WAIT(0); __syncthreads(); KA_CONSUME(23);

        // reduce across the 8 sub-lanes (xor 1,2,4 stay inside the octet)
        #pragma unroll
        for (int tt = 0; tt < 4; tt++)
            #pragma unroll
            for (int j = 0; j < 6; j++) {
                u64 v = acc[tt][j];
                v = add2(v, __shfl_xor_sync(0xffffffffu, v, 1));
                v = add2(v, __shfl_xor_sync(0xffffffffu, v, 2));
                v = add2(v, __shfl_xor_sync(0xffffffffu, v, 4));
                acc[tt][j] = v;
            }

        if (sub == 0) {
            #pragma unroll
            for (int tt = 0; tt < 4; tt++) {
                int tok = tokBase + tbase + 4 * tt;
                float* ls = g_acc + (size_t)(wb + m * W + wid[tok]) * 13;
                #pragma unroll
                for (int j = 0; j < 6; j++) {
                    float2 f = unpack2(acc[tt][j]);
                    atomicAdd(ls + 2 * j,     f.x);
                    atomicAdd(ls + 2 * j + 1, f.y);
                }
                atomicAdd(ls + 12, 1.0f);
            }
        }
        __syncthreads();   // protect s_t and stage buffers before next chunk
    }
}

// ---------------------------------------------------------------------------
// Kernel B: per sample — scope softmax -> importance, masked word softmax ->
// per-word coefficient weight/count; writes q/p logits. 144 blocks x 128.
// ---------------------------------------------------------------------------
__global__ __launch_bounds__(128) void kB(const float* __restrict__ projb,
                                          const float* __restrict__ simp,
                                          float* __restrict__ out)
{
    const int blk = blockIdx.x;
    int W, wb; float* lout = nullptr;
    if (blk < 16)      { W = 200; wb = blk * 200;                    lout = out + OFF_QLOG + blk * 200 * 12; }
    else if (blk < 32) { int m = blk - 16; W = 400; wb = 3200 + m * 400; lout = out + OFF_PLOG + m * 400 * 12; }
    else               { int m = blk - 32; W = 400; wb = 9600 + m * 400; }

    __shared__ float impbuf[400];
    __shared__ float red[4];
    const int tid = threadIdx.x;

    float b[12], si[12];
    #pragma unroll
    for (int s = 0; s < 12; s++) { b[s] = projb[s]; si[s] = simp[s]; }

    for (int w = tid; w < W; w += 128) {
        const float* ls = g_acc + (size_t)(wb + w) * 13;
        float c = ls[12];
        float imp;
        if (c > 0.f) {
            float l[12], mx = -1e30f;
            float invc = 1.f / c;
            #pragma unroll
            for (int s = 0; s < 12; s++) {
                l[s] = ls[s] * invc + b[s];
                mx = fmaxf(mx, l[s]);
            }
            float se = 0.f, ai = 0.f;
            #pragma unroll
            for (int s = 0; s < 12; s++) {
                float e = __expf(l[s] - mx);
                se += e; ai += e * si[s];
            }
            imp = ai / se;
            if (lout) {
                #pragma unroll
                for (int s = 0; s < 12; s++) lout[w * 12 + s] = l[s];
            }
        } else {
            imp = -1e4f;
            if (lout) {
                #pragma unroll
                for (int s = 0; s < 12; s++) lout[w * 12 + s] = 0.f;
            }
        }
        impbuf[w] = imp;
    }
    __syncthreads();

    float mx = -1e30f;
    for (int w = tid; w < W; w += 128) mx = fmaxf(mx, impbuf[w]);
    #pragma unroll
    for (int o = 16; o; o >>= 1) mx = fmaxf(mx, __shfl_xor_sync(0xffffffffu, mx, o));
    if ((tid & 31) == 0) red[tid >> 5] = mx;
    __syncthreads();
    mx = fmaxf(fmaxf(red[0], red[1]), fmaxf(red[2], red[3]));
    __syncthreads();

    float se = 0.f;
    for (int w = tid; w < W; w += 128) se += __expf(impbuf[w] - mx);
    #pragma unroll
    for (int o = 16; o; o >>= 1) se += __shfl_xor_sync(0xffffffffu, se, o);
    if ((tid & 31) == 0) red[tid >> 5] = se;
    __syncthreads();
    se = red[0] + red[1] + red[2] + red[3];
    const float inv = 1.f / se;

    for (int w = tid; w < W; w += 128) {
        float c = g_acc[(size_t)(wb + w) * 13 + 12];
        g_coef[wb + w] = (c > 0.f) ? (__expf(impbuf[w] - mx) * inv) / c : 0.f;
    }
}

// ---------------------------------------------------------------------------
// Kernel C: pooled[m,:] += sum over 64-token slab coef[m, wid] * h[m,tok,:]
// 1088 blocks x 192 threads, float4/thread, streaming loads, unroll 8.
// ---------------------------------------------------------------------------
__global__ __launch_bounds__(192) void kC(
    const float* __restrict__ qh, const float* __restrict__ ph, const float* __restrict__ nh,
    const int* __restrict__ qw, const int* __restrict__ pw, const int* __restrict__ nwid,
    float* __restrict__ out)
{
    const int blk = blockIdx.x;
    const float* hid; const int* wid; int L, wb, m, slab; float* po;
    if (blk < 64)       { m = blk >> 2;  slab = blk & 3; hid = qh; wid = qw;   L = 256; wb = m * 200;        po = out + OFF_QPOOL + m * 768; }
    else if (blk < 192) { int b2 = blk - 64;  m = b2 >> 3; slab = b2 & 7; hid = ph; wid = pw;   L = 512; wb = 3200 + m * 400; po = out + OFF_PPOOL + m * 768; }
    else                { int b2 = blk - 192; m = b2 >> 3; slab = b2 & 7; hid = nh; wid = nwid; L = 512; wb = 9600 + m * 400; po = out + OFF_NPOOL + m * 768; }

    __shared__ float cf[64];
    const int tid = threadIdx.x;
    const int t0 = slab * 64;
    if (tid < 64) cf[tid] = g_coef[wb + wid[m * L + t0 + tid]];
    __syncthreads();

    const float* hp = hid + (size_t)(m * L + t0) * 768 + tid * 4;
    float ax = 0.f, ay = 0.f, az = 0.f, aw = 0.f;
    #pragma unroll 8
    for (int t = 0; t < 64; t++) {
        float c = cf[t];
        float4 v = __ldcs((const float4*)(hp + (size_t)t * 768));
        ax += c * v.x; ay += c * v.y; az += c * v.z; aw += c * v.w;
    }
    float* o = po + tid * 4;
    atomicAdd(o + 0, ax);
    atomicAdd(o + 1, ay);
    atomicAdd(o + 2, az);
    atomicAdd(o + 3, aw);
}

// ---------------------------------------------------------------------------
extern "C" void kernel_launch(void* const* d_in, const int* in_sizes, int n_in,
                              void* d_out, int out_size)
{
    const float* qh    = (const float*)d_in[0];
    const float* ph    = (const float*)d_in[1];
    const float* nh    = (const float*)d_in[2];
    const float* projw = (const float*)d_in[3];
    const float* projb = (const float*)d_in[4];
    const float* simp  = (const float*)d_in[5];
    const int*   qw    = (const int*)d_in[6];
    const int*   pw    = (const int*)d_in[7];
    const int*   nwid  = (const int*)d_in[8];
    float* out = (float*)d_out;

    cudaFuncSetAttribute(kA, cudaFuncAttributeMaxDynamicSharedMemorySize, KA_SMEM);

    void* pacc = nullptr; cudaGetSymbolAddress(&pacc, g_acc);
    void* ptck = nullptr; cudaGetSymbolAddress(&ptck, g_ticket);
    cudaMemsetAsync(pacc, 0, sizeof(float) * TOTAL_WORDS * 13);
    cudaMemsetAsync(ptck, 0, sizeof(unsigned));
    cudaMemsetAsync(out + OFF_QPOOL, 0, sizeof(float) * 24576);   // q_pooled + p_pooled
    cudaMemsetAsync(out + OFF_NPOOL, 0, sizeof(float) * 86016);   // n_pooled

    kA<<<KA_BLOCKS, 256, KA_SMEM>>>(qh, ph, nh, qw, pw, nwid, projw);
    kB<<<144, 128>>>(projb, simp, out);
    kC<<<1088, 192>>>(qh, ph, nh, qw, pw, nwid, out);
}

// round 9
// speedup vs baseline: 1.1441x; 1.0566x over previous
#include <cuda_runtime.h>

// ---------------------------------------------------------------------------
// B=16, N=7, Lq=256, Lp=512, D=768, S=12, Wq=200, Wp=400
// word slots: q 3200, p 6400, n 44800 -> 54400
// out floats: q_pooled[0,12288) p_pooled[12288,24576)
//             q_logits[24576,62976) p_logits[62976,139776) n_pooled[139776,225792)
// ---------------------------------------------------------------------------
#define TOTAL_WORDS 54400
#define OFF_QPOOL 0
#define OFF_PPOOL 12288
#define OFF_QLOG  24576
#define OFF_PLOG  62976
#define OFF_NPOOL 139776

__device__ float g_acc[TOTAL_WORDS * 13];   // 12 logit sums + count
__device__ float g_coef[TOTAL_WORDS];
__device__ unsigned g_ticket;

typedef unsigned long long u64;

__device__ __forceinline__ u64 pack2(float x) {
    u64 r; asm("mov.b64 %0, {%1, %1};" : "=l"(r) : "f"(x)); return r;
}
__device__ __forceinline__ u64 pack2(float lo, float hi) {
    u64 r; asm("mov.b64 %0, {%1, %2};" : "=l"(r) : "f"(lo), "f"(hi)); return r;
}
__device__ __forceinline__ void fma2(u64& a, u64 x, u64 y) {
    asm("fma.rn.f32x2 %0, %1, %2, %0;" : "+l"(a) : "l"(x), "l"(y));
}
__device__ __forceinline__ u64 add2(u64 x, u64 y) {
    u64 r; asm("add.rn.f32x2 %0, %1, %2;" : "=l"(r) : "l"(x), "l"(y)); return r;
}
__device__ __forceinline__ float2 unpack2(u64 v) {
    float2 r; asm("mov.b64 {%0, %1}, %2;" : "=f"(r.x), "=f"(r.y) : "l"(v)); return r;
}

// ---------------------------------------------------------------------------
// Kernel A: per-token projection h[768]@W[768x12] + segment atomics.
// WARP-PRIVATE cp.async rings, NO block barriers in the mainloop:
//   - 256-thread CTAs, 2 CTAs/SM -> 16 fully independent warp streams/SM
//   - each warp: 16 tokens/pass; private 4-stage x 2KB smem ring
//   - stage(i) = bytes [i*128, (i+1)*128) of the 16 token rows
//   - sync = cp.async.wait_group + __syncwarp only (per-warp, cheap)
//   - in-flight ~3 stages x 2KB x 16 warps = 96KB/SM >> latency-BW product
// Staging: lane j-op covers 4 tokens x full 128B line (4 wavefronts, optimal).
// Consume: 4 conflict-free LDS.128 per i (512B contiguous each).
// Weights: smem chunks [c][k*6+j], pitch 26 u64 (39936B); per k 3x LDS.128,
//   sub offsets mod 128 = {0,80,32,112,64,16,96,48}, 4-way grp broadcast.
// Dynamic smem: 39936 + 8 warps * 8192 = 105472B -> 2 CTAs/SM.
// ---------------------------------------------------------------------------
#define WSLOT 26
#define NPASS_TOTAL 4352     // 69632 tokens / 16
#define KA_BLOCKS 296        // 148 SM * 2
#define KA_SMEM (39936 + 8 * 8192)

__device__ __forceinline__ void cp16(unsigned dst, const void* src) {
    asm volatile("cp.async.cg.shared.global [%0], [%1], 16;" :: "r"(dst), "l"(src));
}

#define KA_ISSUE(S)                                                            \
    {                                                                          \
        const unsigned st = ring_u32 + ((S) & 3) * 2048;                       \
        _Pragma("unroll")                                                      \
        for (int j = 0; j < 4; j++) {                                          \
            cp16(st + (grp + 4 * j) * 128 + sub * 16,                          \
                 hb + (size_t)(grp + 4 * j) * 768 + (S) * 32 + sub * 4);       \
        }                                                                      \
        asm volatile("cp.async.commit_group;" ::: "memory");                   \
    }

#define KA_WAIT(N) asm volatile("cp.async.wait_group %0;" :: "n"(N) : "memory")

#define KA_CONSUME(I)                                                          \
    {                                                                          \
        const char* bp = ringc + ((I) & 3) * 2048 + grp * 128 + sub * 16;      \
        float4 A0 = *(const float4*)(bp);                                      \
        float4 A1 = *(const float4*)(bp + 512);                                \
        float4 A2 = *(const float4*)(bp + 1024);                               \
        float4 A3 = *(const float4*)(bp + 1536);                               \
        const u64* wr = swl + (I) * (8 * WSLOT);                               \
        _Pragma("unroll")                                                      \
        for (int k = 0; k < 4; k++) {                                          \
            u64 h0 = pack2(((const float*)&A0)[k]);                            \
            u64 h1 = pack2(((const float*)&A1)[k]);                            \
            u64 hv2 = pack2(((const float*)&A2)[k]);                           \
            u64 h3 = pack2(((const float*)&A3)[k]);                            \
            ulonglong2 w01 = *(const ulonglong2*)(wr + k * 6);                 \
            ulonglong2 w23 = *(const ulonglong2*)(wr + k * 6 + 2);             \
            ulonglong2 w45 = *(const ulonglong2*)(wr + k * 6 + 4);             \
            fma2(acc[0][0], h0, w01.x); fma2(acc[0][1], h0, w01.y);            \
            fma2(acc[0][2], h0, w23.x); fma2(acc[0][3], h0, w23.y);            \
            fma2(acc[0][4], h0, w45.x); fma2(acc[0][5], h0, w45.y);            \
            fma2(acc[1][0], h1, w01.x); fma2(acc[1][1], h1, w01.y);            \
            fma2(acc[1][2], h1, w23.x); fma2(acc[1][3], h1, w23.y);            \
            fma2(acc[1][4], h1, w45.x); fma2(acc[1][5], h1, w45.y);            \
            fma2(acc[2][0], hv2, w01.x); fma2(acc[2][1], hv2, w01.y);          \
            fma2(acc[2][2], hv2, w23.x); fma2(acc[2][3], hv2, w23.y);          \
            fma2(acc[2][4], hv2, w45.x); fma2(acc[2][5], hv2, w45.y);          \
            fma2(acc[3][0], h3, w01.x); fma2(acc[3][1], h3, w01.y);            \
            fma2(acc[3][2], h3, w23.x); fma2(acc[3][3], h3, w23.y);            \
            fma2(acc[3][4], h3, w45.x); fma2(acc[3][5], h3, w45.y);            \
        }                                                                      \
    }

__global__ __launch_bounds__(256, 2) void kA(
    const float* __restrict__ qh, const float* __restrict__ ph, const float* __restrict__ nh,
    const int* __restrict__ qw, const int* __restrict__ pw, const int* __restrict__ nwid,
    const float* __restrict__ projw)
{
    extern __shared__ __align__(16) char dsm[];
    u64* sw = (u64*)dsm;                       // 39936 B weight table
    char* hbuf = dsm + 39936;                  // 8 warps x 8KB rings

    for (int idx = threadIdx.x; idx < 768 * 6; idx += 256) {
        int d = idx / 6, j = idx % 6;
        sw[(d >> 2) * WSLOT + (d & 3) * 6 + j] =
            pack2(projw[d * 12 + 2 * j], projw[d * 12 + 2 * j + 1]);
    }
    __syncthreads();

    const int tid  = threadIdx.x;
    const int lane = tid & 31;
    const int wrp  = tid >> 5;     // 0..7
    const int sub  = lane & 7;
    const int grp  = lane >> 3;
    const u64* swl = sw + sub * WSLOT;
    const char* ringc = hbuf + wrp * 8192;

    unsigned ring_u32;
    {
        unsigned base;
        asm("{ .reg .u64 t; cvta.to.shared.u64 t, %1; cvt.u32.u64 %0, t; }"
            : "=r"(base) : "l"(ringc));
        ring_u32 = base;
    }

    for (;;) {
        unsigned t;
        if (lane == 0) t = atomicAdd(&g_ticket, 1u);
        t = __shfl_sync(0xffffffffu, t, 0);
        if (t >= NPASS_TOTAL) break;
        const int p = (int)t;

        const float* hid; const int* wid; int logL, W, wb, lp;
        if (p < 256)      { hid = qh; wid = qw;   logL = 8; W = 200; wb = 0;    lp = p; }
        else if (p < 768) { hid = ph; wid = pw;   logL = 9; W = 400; wb = 3200; lp = p - 256; }
        else              { hid = nh; wid = nwid; logL = 9; W = 400; wb = 9600; lp = p - 768; }

        const int tokBase = lp << 4;                 // 16 tokens
        const int m = tokBase >> logL;
        const float* hb = hid + (size_t)tokBase * 768;

        u64 acc[4][6];
        #pragma unroll
        for (int tt = 0; tt < 4; tt++)
            #pragma unroll
            for (int j = 0; j < 6; j++) acc[tt][j] = 0ull;

        KA_ISSUE(0); KA_ISSUE(1); KA_ISSUE(2);

        #pragma unroll 1
        for (int i = 0; i < 21; i++) {
            KA_WAIT(2);
            __syncwarp();
            KA_CONSUME(i);
            KA_ISSUE(i + 3);
        }
        KA_WAIT(2); __syncwarp(); KA_CONSUME(21);
        KA_WAIT(1); __syncwarp(); KA_CONSUME(22);
        KA_WAIT(0); __syncwarp(); KA_CONSUME(23);

        // reduce across the 8 sub-lanes (xor 1,2,4 stay inside the octet)
        #pragma unroll
        for (int tt = 0; tt < 4; tt++)
            #pragma unroll
            for (int j = 0; j < 6; j++) {
                u64 v = acc[tt][j];
                v = add2(v, __shfl_xor_sync(0xffffffffu, v, 1));
                v = add2(v, __shfl_xor_sync(0xffffffffu, v, 2));
                v = add2(v, __shfl_xor_sync(0xffffffffu, v, 4));
                acc[tt][j] = v;
            }

        if (sub == 0) {
            #pragma unroll
            for (int tt = 0; tt < 4; tt++) {
                int tok = tokBase + grp + 4 * tt;
                float* ls = g_acc + (size_t)(wb + m * W + wid[tok]) * 13;
                #pragma unroll
                for (int j = 0; j < 6; j++) {
                    float2 f = unpack2(acc[tt][j]);
                    atomicAdd(ls + 2 * j,     f.x);
                    atomicAdd(ls + 2 * j + 1, f.y);
                }
                atomicAdd(ls + 12, 1.0f);
            }
        }
    }
}

// ---------------------------------------------------------------------------
// Kernel B: per sample — scope softmax -> importance, masked word softmax ->
// per-word coefficient weight/count; writes q/p logits. 144 blocks x 128.
// ---------------------------------------------------------------------------
__global__ __launch_bounds__(128) void kB(const float* __restrict__ projb,
                                          const float* __restrict__ simp,
                                          float* __restrict__ out)
{
    const int blk = blockIdx.x;
    int W, wb; float* lout = nullptr;
    if (blk < 16)      { W = 200; wb = blk * 200;                    lout = out + OFF_QLOG + blk * 200 * 12; }
    else if (blk < 32) { int m = blk - 16; W = 400; wb = 3200 + m * 400; lout = out + OFF_PLOG + m * 400 * 12; }
    else               { int m = blk - 32; W = 400; wb = 9600 + m * 400; }

    __shared__ float impbuf[400];
    __shared__ float red[4];
    const int tid = threadIdx.x;

    float b[12], si[12];
    #pragma unroll
    for (int s = 0; s < 12; s++) { b[s] = projb[s]; si[s] = simp[s]; }

    for (int w = tid; w < W; w += 128) {
        const float* ls = g_acc + (size_t)(wb + w) * 13;
        float c = ls[12];
        float imp;
        if (c > 0.f) {
            float l[12], mx = -1e30f;
            float invc = 1.f / c;
            #pragma unroll
            for (int s = 0; s < 12; s++) {
                l[s] = ls[s] * invc + b[s];
                mx = fmaxf(mx, l[s]);
            }
            float se = 0.f, ai = 0.f;
            #pragma unroll
            for (int s = 0; s < 12; s++) {
                float e = __expf(l[s] - mx);
                se += e; ai += e * si[s];
            }
            imp = ai / se;
            if (lout) {
                #pragma unroll
                for (int s = 0; s < 12; s++) lout[w * 12 + s] = l[s];
            }
        } else {
            imp = -1e4f;
            if (lout) {
                #pragma unroll
                for (int s = 0; s < 12; s++) lout[w * 12 + s] = 0.f;
            }
        }
        impbuf[w] = imp;
    }
    __syncthreads();

    float mx = -1e30f;
    for (int w = tid; w < W; w += 128) mx = fmaxf(mx, impbuf[w]);
    #pragma unroll
    for (int o = 16; o; o >>= 1) mx = fmaxf(mx, __shfl_xor_sync(0xffffffffu, mx, o));
    if ((tid & 31) == 0) red[tid >> 5] = mx;
    __syncthreads();
    mx = fmaxf(fmaxf(red[0], red[1]), fmaxf(red[2], red[3]));
    __syncthreads();

    float se = 0.f;
    for (int w = tid; w < W; w += 128) se += __expf(impbuf[w] - mx);
    #pragma unroll
    for (int o = 16; o; o >>= 1) se += __shfl_xor_sync(0xffffffffu, se, o);
    if ((tid & 31) == 0) red[tid >> 5] = se;
    __syncthreads();
    se = red[0] + red[1] + red[2] + red[3];
    const float inv = 1.f / se;

    for (int w = tid; w < W; w += 128) {
        float c = g_acc[(size_t)(wb + w) * 13 + 12];
        g_coef[wb + w] = (c > 0.f) ? (__expf(impbuf[w] - mx) * inv) / c : 0.f;
    }
}

// ---------------------------------------------------------------------------
// Kernel C: pooled[m,:] += sum over 64-token slab coef[m, wid] * h[m,tok,:]
// 1088 blocks x 192 threads, float4/thread, streaming loads, unroll 8.
// ---------------------------------------------------------------------------
__global__ __launch_bounds__(192) void kC(
    const float* __restrict__ qh, const float* __restrict__ ph, const float* __restrict__ nh,
    const int* __restrict__ qw, const int* __restrict__ pw, const int* __restrict__ nwid,
    float* __restrict__ out)
{
    const int blk = blockIdx.x;
    const float* hid; const int* wid; int L, wb, m, slab; float* po;
    if (blk < 64)       { m = blk >> 2;  slab = blk & 3; hid = qh; wid = qw;   L = 256; wb = m * 200;        po = out + OFF_QPOOL + m * 768; }
    else if (blk < 192) { int b2 = blk - 64;  m = b2 >> 3; slab = b2 & 7; hid = ph; wid = pw;   L = 512; wb = 3200 + m * 400; po = out + OFF_PPOOL + m * 768; }
    else                { int b2 = blk - 192; m = b2 >> 3; slab = b2 & 7; hid = nh; wid = nwid; L = 512; wb = 9600 + m * 400; po = out + OFF_NPOOL + m * 768; }

    __shared__ float cf[64];
    const int tid = threadIdx.x;
    const int t0 = slab * 64;
    if (tid < 64) cf[tid] = g_coef[wb + wid[m * L + t0 + tid]];
    __syncthreads();

    const float* hp = hid + (size_t)(m * L + t0) * 768 + tid * 4;
    float ax = 0.f, ay = 0.f, az = 0.f, aw = 0.f;
    #pragma unroll 8
    for (int t = 0; t < 64; t++) {
        float c = cf[t];
        float4 v = __ldcs((const float4*)(hp + (size_t)t * 768));
        ax += c * v.x; ay += c * v.y; az += c * v.z; aw += c * v.w;
    }
    float* o = po + tid * 4;
    atomicAdd(o + 0, ax);
    atomicAdd(o + 1, ay);
    atomicAdd(o + 2, az);
    atomicAdd(o + 3, aw);
}

// ---------------------------------------------------------------------------
extern "C" void kernel_launch(void* const* d_in, const int* in_sizes, int n_in,
                              void* d_out, int out_size)
{
    const float* qh    = (const float*)d_in[0];
    const float* ph    = (const float*)d_in[1];
    const float* nh    = (const float*)d_in[2];
    const float* projw = (const float*)d_in[3];
    const float* projb = (const float*)d_in[4];
    const float* simp  = (const float*)d_in[5];
    const int*   qw    = (const int*)d_in[6];
    const int*   pw    = (const int*)d_in[7];
    const int*   nwid  = (const int*)d_in[8];
    float* out = (float*)d_out;

    cudaFuncSetAttribute(kA, cudaFuncAttributeMaxDynamicSharedMemorySize, KA_SMEM);

    void* pacc = nullptr; cudaGetSymbolAddress(&pacc, g_acc);
    void* ptck = nullptr; cudaGetSymbolAddress(&ptck, g_ticket);
    cudaMemsetAsync(pacc, 0, sizeof(float) * TOTAL_WORDS * 13);
    cudaMemsetAsync(ptck, 0, sizeof(unsigned));
    cudaMemsetAsync(out + OFF_QPOOL, 0, sizeof(float) * 24576);   // q_pooled + p_pooled
    cudaMemsetAsync(out + OFF_NPOOL, 0, sizeof(float) * 86016);   // n_pooled

    kA<<<KA_BLOCKS, 256, KA_SMEM>>>(qh, ph, nh, qw, pw, nwid, projw);
    kB<<<144, 128>>>(projb, simp, out);
    kC<<<1088, 192>>>(qh, ph, nh, qw, pw, nwid, out);
}